// round 3
// baseline (speedup 1.0000x reference)
#include <cuda_runtime.h>
#include <math.h>

#define S_ 512
#define B_ 64
#define I_ 256
#define H_ 1024
#define L_ 3
#define BH_ (B_ * H_)      // 65536
#define LBH_ (L_ * BH_)    // 196608

#define N_PRE_ITEMS (S_ * 64)   // 32768: (s, colTile16) for X@W_xh
#define N_STEP_ITEMS 192        // 128 heavy (L1/L2 colTile16) + 64 light (L0 colTile16)

// -------- scratch (static device memory; no runtime allocation) --------
__device__ float g_P[(size_t)S_ * B_ * H_];   // precomputed X@W_xh + b_h
__device__ float g_h[2][LBH_];                // double-buffered hidden state
__device__ int g_ctr_pre;
__device__ int g_ctr[S_];
__device__ unsigned g_cnt;
__device__ volatile unsigned g_gen;

typedef unsigned long long ull;

__device__ __forceinline__ void ffma2(ull& d, ull a, ull b) {
    // packed 2xfp32 FMA: d = a*b + d  (element-wise on the two lanes)
    asm volatile("fma.rn.f32x2 %0, %1, %2, %0;" : "+l"(d) : "l"(a), "l"(b));
}
__device__ __forceinline__ float2 unpk(ull v) {
    float2 r;
    asm("mov.b64 {%0, %1}, %2;" : "=f"(r.x), "=f"(r.y) : "l"(v));
    return r;
}

// -------- software grid barrier (all blocks resident; grid = #SMs) --------
__device__ __forceinline__ void grid_sync(unsigned nb) {
    __syncthreads();
    if (threadIdx.x == 0) {
        __threadfence();                 // make this block's stores visible
        unsigned g = g_gen;
        if (atomicAdd(&g_cnt, 1u) == nb - 1u) {
            g_cnt = 0;
            __threadfence();
            g_gen = g + 1u;
        } else {
            while (g_gen == g) { }
        }
    }
    __syncthreads();
}

// -------- 64x16 output tile, K-loop GEMM core (fp32, FFMA2) --------
// A[b][k] = A + b*lda + k   (64 rows, read via ld.cg -> L2-fresh)
// W[k][c] = W + k*ldw + colbase + c  (immutable weights, ld.g/L1)
// Accumulates into a00,a01 (row r0; even-k / odd-k chains) and a10,a11 (row r1).
// SMEM layouts (padded stride 132 words -> bank-conflict-free LDS.128):
//   sh_h[b*132 + 2k + {0,1}] = A[b][k] duplicated  (FFMA2 "a" operand, no packing)
//   sh_w[(c/2)*132 + 2k + (c&1)] = W[k][c]          (FFMA2 "b" operand pairs)
__device__ __forceinline__ void load_chunk_regs(
    const float* __restrict__ A, int lda,
    const float* __restrict__ W, int ldw,
    int k0, int colbase, float hv[16], float wv[4])
{
    const int tid = threadIdx.x;
#pragma unroll
    for (int it = 0; it < 16; ++it) {
        int idx = tid + (it << 8);
        int b = idx >> 6, kk = idx & 63;
        hv[it] = __ldcg(A + b * lda + k0 + kk);
    }
#pragma unroll
    for (int it = 0; it < 4; ++it) {
        int idx = tid + (it << 8);
        int kk = idx >> 4, c = idx & 15;
        wv[it] = __ldg(&W[(size_t)(k0 + kk) * ldw + colbase + c]);
    }
}

__device__ __forceinline__ void mm64x16(
    const float* __restrict__ A, int lda,
    const float* __restrict__ W, int ldw,
    int K, int colbase,
    float* sh_h, float* sh_w,
    ull& a00, ull& a01, ull& a10, ull& a11)
{
    const int tid = threadIdx.x;
    const int warp = tid >> 5, lane = tid & 31;
    const int r0 = (warp << 2) + (lane >> 3);   // 0..31
    const int cp = lane & 7;                    // column pair 0..7

    const ulonglong2* hp0 = (const ulonglong2*)(sh_h + r0 * 132);
    const ulonglong2* hp1 = (const ulonglong2*)(sh_h + (r0 + 32) * 132);
    const ulonglong2* wp  = (const ulonglong2*)(sh_w + cp * 132);

    float hv[16], wv[4];
    load_chunk_regs(A, lda, W, ldw, 0, colbase, hv, wv);

    const int nch = K >> 6;     // KC = 64
    for (int ch = 0; ch < nch; ++ch) {
        __syncthreads();        // previous consumers of smem are done
        // registers -> smem (duplicated h, paired w)
        float2* shh2 = (float2*)sh_h;
#pragma unroll
        for (int it = 0; it < 16; ++it) {
            int idx = tid + (it << 8);
            int b = idx >> 6, kk = idx & 63;
            shh2[b * 66 + kk] = make_float2(hv[it], hv[it]);
        }
#pragma unroll
        for (int it = 0; it < 4; ++it) {
            int idx = tid + (it << 8);
            int kk = idx >> 4, c = idx & 15;
            sh_w[(c >> 1) * 132 + (kk << 1) + (c & 1)] = wv[it];
        }
        __syncthreads();
        if (ch + 1 < nch)       // prefetch next chunk (overlaps compute)
            load_chunk_regs(A, lda, W, ldw, (ch + 1) << 6, colbase, hv, wv);
        // compute 64 K-steps: per iter 3x LDS.128 + 4x FFMA2 (16 FMA)
#pragma unroll
        for (int kk2 = 0; kk2 < 32; ++kk2) {
            ulonglong2 h0 = hp0[kk2];
            ulonglong2 h1 = hp1[kk2];
            ulonglong2 w2 = wp[kk2];
            ffma2(a00, h0.x, w2.x);
            ffma2(a01, h0.y, w2.y);
            ffma2(a10, h1.x, w2.x);
            ffma2(a11, h1.y, w2.y);
        }
    }
}

// -------- persistent kernel: phase-0 precompute + 512 recurrent steps --------
__global__ void __launch_bounds__(256, 1) rnn_persistent(
    const float* __restrict__ X, const float* __restrict__ W_xh,
    const float* __restrict__ W_hh, const float* __restrict__ b_h,
    const float* __restrict__ W_layers, const float* __restrict__ U_layers,
    const float* __restrict__ b_layers, float* __restrict__ out,
    int nblocks, int out_size)
{
    __shared__ __align__(16) float sh_h[64 * 132];
    __shared__ __align__(16) float sh_w[8 * 132];
    __shared__ int s_item;

    const int tid = threadIdx.x;
    const int warp = tid >> 5, lane = tid & 31;
    const int r0 = (warp << 2) + (lane >> 3);
    const int r1 = r0 + 32;
    const int cp = lane & 7;
    const bool want_hfinal = (out_size >= (int)((size_t)S_ * BH_ + LBH_));

    // ---- phase 0: g_P = X @ W_xh + b_h ----
    for (;;) {
        if (tid == 0) s_item = atomicAdd(&g_ctr_pre, 1);
        __syncthreads();
        int t = s_item;
        if (t >= N_PRE_ITEMS) break;
        int s = t >> 6, colb = (t & 63) << 4;
        ull a00 = 0, a01 = 0, a10 = 0, a11 = 0;
        mm64x16(X + (size_t)s * B_ * I_, I_, W_xh, H_, I_, colb,
                sh_h, sh_w, a00, a01, a10, a11);
        int c = colb + (cp << 1);
        float bh0 = b_h[c], bh1 = b_h[c + 1];
        float2 u0 = unpk(a00), u1 = unpk(a01), v0 = unpk(a10), v1 = unpk(a11);
        float* Ps = g_P + (size_t)s * BH_;
        *(float2*)&Ps[r0 * H_ + c] = make_float2(u0.x + u1.x + bh0, u0.y + u1.y + bh1);
        *(float2*)&Ps[r1 * H_ + c] = make_float2(v0.x + v1.x + bh0, v0.y + v1.y + bh1);
    }
    grid_sync(nblocks);

    // ---- recurrence ----
    for (int s = 0; s < S_; ++s) {
        const float* hold = g_h[s & 1];
        float* hnew = g_h[(s & 1) ^ 1];
        for (;;) {
            if (tid == 0) s_item = atomicAdd(&g_ctr[s], 1);
            __syncthreads();
            int t = s_item;
            if (t >= N_STEP_ITEMS) break;
            // heavy items (layers 1..2, cost 2) first for greedy balance
            int layer, ct;
            if (t < 128) { layer = 1 + (t & 1); ct = t >> 1; }
            else         { layer = 0;           ct = t - 128; }
            int colb = ct << 4;
            ull a00 = 0, a01 = 0, a10 = 0, a11 = 0;
            if (layer == 0) {
                mm64x16(hold, H_, W_hh, H_, H_, colb, sh_h, sh_w, a00, a01, a10, a11);
            } else {
                const float* Um = U_layers + (size_t)(layer - 1) * H_ * H_;
                const float* Wm = W_layers + (size_t)(layer - 1) * H_ * H_;
                mm64x16(hold + (size_t)layer * BH_,       H_, Um, H_, H_, colb,
                        sh_h, sh_w, a00, a01, a10, a11);
                mm64x16(hold + (size_t)(layer - 1) * BH_, H_, Wm, H_, H_, colb,
                        sh_h, sh_w, a00, a01, a10, a11);
            }
            int c = colb + (cp << 1);
            float2 u0 = unpk(a00), u1 = unpk(a01), v0 = unpk(a10), v1 = unpk(a11);
            float p00, p01, p10, p11;
            if (layer == 0) {
                const float* Ps = g_P + (size_t)s * BH_;
                float2 q0 = *(const float2*)&Ps[r0 * H_ + c];
                float2 q1 = *(const float2*)&Ps[r1 * H_ + c];
                p00 = q0.x; p01 = q0.y; p10 = q1.x; p11 = q1.y;
            } else {
                float bb0 = b_layers[(layer - 1) * H_ + c];
                float bb1 = b_layers[(layer - 1) * H_ + c + 1];
                p00 = bb0; p01 = bb1; p10 = bb0; p11 = bb1;
            }
            float o00 = tanhf(u0.x + u1.x + p00);
            float o01 = tanhf(u0.y + u1.y + p01);
            float o10 = tanhf(v0.x + v1.x + p10);
            float o11 = tanhf(v0.y + v1.y + p11);

            float* hn = hnew + (size_t)layer * BH_;
            __stcg((float2*)&hn[r0 * H_ + c], make_float2(o00, o01));
            __stcg((float2*)&hn[r1 * H_ + c], make_float2(o10, o11));
            if (layer == 2) {
                float* os = out + (size_t)s * BH_;
                *(float2*)&os[r0 * H_ + c] = make_float2(o00, o01);
                *(float2*)&os[r1 * H_ + c] = make_float2(o10, o11);
            }
            if (s == S_ - 1 && want_hfinal) {
                float* hf = out + (size_t)S_ * BH_ + (size_t)layer * BH_;
                *(float2*)&hf[r0 * H_ + c] = make_float2(o00, o01);
                *(float2*)&hf[r1 * H_ + c] = make_float2(o10, o11);
            }
        }
        grid_sync(nblocks);
    }
}

__global__ void rnn_init() {
    int idx = blockIdx.x * blockDim.x + threadIdx.x;
    int stride = gridDim.x * blockDim.x;
    if (idx == 0) g_ctr_pre = 0;
    if (idx < S_) g_ctr[idx] = 0;
    for (int i = idx; i < LBH_; i += stride) g_h[0][i] = 0.0f;
}

extern "C" void kernel_launch(void* const* d_in, const int* in_sizes, int n_in,
                              void* d_out, int out_size) {
    const float* X    = (const float*)d_in[0];
    const float* W_xh = (const float*)d_in[1];
    const float* W_hh = (const float*)d_in[2];
    const float* b_h  = (const float*)d_in[3];
    const float* W_l  = (const float*)d_in[4];
    const float* U_l  = (const float*)d_in[5];
    const float* b_l  = (const float*)d_in[6];
    float* out = (float*)d_out;

    int nsm = 148;
    cudaDeviceGetAttribute(&nsm, cudaDevAttrMultiProcessorCount, 0);
    if (nsm < 1) nsm = 148;
    if (nsm > 512) nsm = 512;

    rnn_init<<<256, 256>>>();
    rnn_persistent<<<nsm, 256>>>(X, W_xh, W_hh, b_h, W_l, U_l, b_l, out,
                                 nsm, out_size);
}

// round 4
// speedup vs baseline: 1.0032x; 1.0032x over previous
#include <cuda_runtime.h>
#include <math.h>

#define S_ 512
#define B_ 64
#define I_ 256
#define H_ 1024
#define L_ 3
#define BH_ (B_ * H_)      // 65536
#define LBH_ (L_ * BH_)    // 196608

#define N_PRE_ITEMS (S_ * 64)   // 32768: (s, colTile16) for X@W_xh
#define N_STEP_ITEMS 192        // 128 heavy (L1/L2 colTile16) + 64 light (L0 colTile16)

// -------- scratch (static device memory; no runtime allocation) --------
__device__ float g_P[(size_t)S_ * B_ * H_];   // precomputed X@W_xh + b_h
__device__ float g_h[2][LBH_];                // double-buffered hidden state
__device__ int g_ctr_pre;
__device__ int g_ctr[S_];
__device__ unsigned g_cnt;
__device__ volatile unsigned g_gen;

typedef unsigned long long ull;

__device__ __forceinline__ void ffma2(ull& d, ull a, ull b) {
    // packed 2xfp32 FMA: d = a*b + d  (element-wise on the two lanes)
    asm volatile("fma.rn.f32x2 %0, %1, %2, %0;" : "+l"(d) : "l"(a), "l"(b));
}
__device__ __forceinline__ float2 unpk(ull v) {
    float2 r;
    asm("mov.b64 {%0, %1}, %2;" : "=f"(r.x), "=f"(r.y) : "l"(v));
    return r;
}

// -------- software grid barrier (all blocks resident; grid = #SMs) --------
__device__ __forceinline__ void grid_sync(unsigned nb) {
    __syncthreads();
    if (threadIdx.x == 0) {
        __threadfence();                 // make this block's stores visible
        unsigned g = g_gen;
        if (atomicAdd(&g_cnt, 1u) == nb - 1u) {
            g_cnt = 0;
            __threadfence();
            g_gen = g + 1u;
        } else {
            while (g_gen == g) { }
        }
    }
    __syncthreads();
}

// -------- 64x16 output tile, K-loop GEMM core (fp32, FFMA2) --------
// A[b][k] = A + b*lda + k   (64 rows, read via ld.cg -> L2-fresh)
// W[k][c] = W + k*ldw + colbase + c  (immutable weights, ld.g/L1)
// Accumulates into a00,a01 (row r0; even-k / odd-k chains) and a10,a11 (row r1).
// SMEM layouts (padded stride 132 words -> bank-conflict-free LDS.128):
//   sh_h[b*132 + 2k + {0,1}] = A[b][k] duplicated  (FFMA2 "a" operand, no packing)
//   sh_w[(c/2)*132 + 2k + (c&1)] = W[k][c]          (FFMA2 "b" operand pairs)
__device__ __forceinline__ void load_chunk_regs(
    const float* __restrict__ A, int lda,
    const float* __restrict__ W, int ldw,
    int k0, int colbase, float hv[16], float wv[4])
{
    const int tid = threadIdx.x;
#pragma unroll
    for (int it = 0; it < 16; ++it) {
        int idx = tid + (it << 8);
        int b = idx >> 6, kk = idx & 63;
        hv[it] = __ldcg(A + b * lda + k0 + kk);
    }
#pragma unroll
    for (int it = 0; it < 4; ++it) {
        int idx = tid + (it << 8);
        int kk = idx >> 4, c = idx & 15;
        wv[it] = __ldg(&W[(size_t)(k0 + kk) * ldw + colbase + c]);
    }
}

__device__ __forceinline__ void mm64x16(
    const float* __restrict__ A, int lda,
    const float* __restrict__ W, int ldw,
    int K, int colbase,
    float* sh_h, float* sh_w,
    ull& a00, ull& a01, ull& a10, ull& a11)
{
    const int tid = threadIdx.x;
    const int warp = tid >> 5, lane = tid & 31;
    const int r0 = (warp << 2) + (lane >> 3);   // 0..31
    const int cp = lane & 7;                    // column pair 0..7

    const ulonglong2* hp0 = (const ulonglong2*)(sh_h + r0 * 132);
    const ulonglong2* hp1 = (const ulonglong2*)(sh_h + (r0 + 32) * 132);
    const ulonglong2* wp  = (const ulonglong2*)(sh_w + cp * 132);

    float hv[16], wv[4];
    load_chunk_regs(A, lda, W, ldw, 0, colbase, hv, wv);

    const int nch = K >> 6;     // KC = 64
    for (int ch = 0; ch < nch; ++ch) {
        __syncthreads();        // previous consumers of smem are done
        // registers -> smem (duplicated h, paired w)
        float2* shh2 = (float2*)sh_h;
#pragma unroll
        for (int it = 0; it < 16; ++it) {
            int idx = tid + (it << 8);
            int b = idx >> 6, kk = idx & 63;
            shh2[b * 66 + kk] = make_float2(hv[it], hv[it]);
        }
#pragma unroll
        for (int it = 0; it < 4; ++it) {
            int idx = tid + (it << 8);
            int kk = idx >> 4, c = idx & 15;
            sh_w[(c >> 1) * 132 + (kk << 1) + (c & 1)] = wv[it];
        }
        __syncthreads();
        if (ch + 1 < nch)       // prefetch next chunk (overlaps compute)
            load_chunk_regs(A, lda, W, ldw, (ch + 1) << 6, colbase, hv, wv);
        // compute 64 K-steps: per iter 3x LDS.128 + 4x FFMA2 (16 FMA)
#pragma unroll
        for (int kk2 = 0; kk2 < 32; ++kk2) {
            ulonglong2 h0 = hp0[kk2];
            ulonglong2 h1 = hp1[kk2];
            ulonglong2 w2 = wp[kk2];
            ffma2(a00, h0.x, w2.x);
            ffma2(a01, h0.y, w2.y);
            ffma2(a10, h1.x, w2.x);
            ffma2(a11, h1.y, w2.y);
        }
    }
}

// -------- persistent kernel: phase-0 precompute + 512 recurrent steps --------
__global__ void __launch_bounds__(256, 1) rnn_persistent(
    const float* __restrict__ X, const float* __restrict__ W_xh,
    const float* __restrict__ W_hh, const float* __restrict__ b_h,
    const float* __restrict__ W_layers, const float* __restrict__ U_layers,
    const float* __restrict__ b_layers, float* __restrict__ out,
    int nblocks, int out_size)
{
    __shared__ __align__(16) float sh_h[64 * 132];
    __shared__ __align__(16) float sh_w[8 * 132];
    __shared__ int s_item;

    const int tid = threadIdx.x;
    const int warp = tid >> 5, lane = tid & 31;
    const int r0 = (warp << 2) + (lane >> 3);
    const int r1 = r0 + 32;
    const int cp = lane & 7;
    const bool want_hfinal = (out_size >= (int)((size_t)S_ * BH_ + LBH_));

    // ---- phase 0: g_P = X @ W_xh + b_h ----
    for (;;) {
        if (tid == 0) s_item = atomicAdd(&g_ctr_pre, 1);
        __syncthreads();
        int t = s_item;
        if (t >= N_PRE_ITEMS) break;
        int s = t >> 6, colb = (t & 63) << 4;
        ull a00 = 0, a01 = 0, a10 = 0, a11 = 0;
        mm64x16(X + (size_t)s * B_ * I_, I_, W_xh, H_, I_, colb,
                sh_h, sh_w, a00, a01, a10, a11);
        int c = colb + (cp << 1);
        float bh0 = b_h[c], bh1 = b_h[c + 1];
        float2 u0 = unpk(a00), u1 = unpk(a01), v0 = unpk(a10), v1 = unpk(a11);
        float* Ps = g_P + (size_t)s * BH_;
        *(float2*)&Ps[r0 * H_ + c] = make_float2(u0.x + u1.x + bh0, u0.y + u1.y + bh1);
        *(float2*)&Ps[r1 * H_ + c] = make_float2(v0.x + v1.x + bh0, v0.y + v1.y + bh1);
    }
    grid_sync(nblocks);

    // ---- recurrence ----
    for (int s = 0; s < S_; ++s) {
        const float* hold = g_h[s & 1];
        float* hnew = g_h[(s & 1) ^ 1];
        for (;;) {
            if (tid == 0) s_item = atomicAdd(&g_ctr[s], 1);
            __syncthreads();
            int t = s_item;
            if (t >= N_STEP_ITEMS) break;
            // heavy items (layers 1..2, cost 2) first for greedy balance
            int layer, ct;
            if (t < 128) { layer = 1 + (t & 1); ct = t >> 1; }
            else         { layer = 0;           ct = t - 128; }
            int colb = ct << 4;
            ull a00 = 0, a01 = 0, a10 = 0, a11 = 0;
            if (layer == 0) {
                mm64x16(hold, H_, W_hh, H_, H_, colb, sh_h, sh_w, a00, a01, a10, a11);
            } else {
                const float* Um = U_layers + (size_t)(layer - 1) * H_ * H_;
                const float* Wm = W_layers + (size_t)(layer - 1) * H_ * H_;
                mm64x16(hold + (size_t)layer * BH_,       H_, Um, H_, H_, colb,
                        sh_h, sh_w, a00, a01, a10, a11);
                mm64x16(hold + (size_t)(layer - 1) * BH_, H_, Wm, H_, H_, colb,
                        sh_h, sh_w, a00, a01, a10, a11);
            }
            int c = colb + (cp << 1);
            float2 u0 = unpk(a00), u1 = unpk(a01), v0 = unpk(a10), v1 = unpk(a11);
            float p00, p01, p10, p11;
            if (layer == 0) {
                const float* Ps = g_P + (size_t)s * BH_;
                float2 q0 = *(const float2*)&Ps[r0 * H_ + c];
                float2 q1 = *(const float2*)&Ps[r1 * H_ + c];
                p00 = q0.x; p01 = q0.y; p10 = q1.x; p11 = q1.y;
            } else {
                float bb0 = b_layers[(layer - 1) * H_ + c];
                float bb1 = b_layers[(layer - 1) * H_ + c + 1];
                p00 = bb0; p01 = bb1; p10 = bb0; p11 = bb1;
            }
            float o00 = tanhf(u0.x + u1.x + p00);
            float o01 = tanhf(u0.y + u1.y + p01);
            float o10 = tanhf(v0.x + v1.x + p10);
            float o11 = tanhf(v0.y + v1.y + p11);

            float* hn = hnew + (size_t)layer * BH_;
            __stcg((float2*)&hn[r0 * H_ + c], make_float2(o00, o01));
            __stcg((float2*)&hn[r1 * H_ + c], make_float2(o10, o11));
            if (layer == 2) {
                float* os = out + (size_t)s * BH_;
                *(float2*)&os[r0 * H_ + c] = make_float2(o00, o01);
                *(float2*)&os[r1 * H_ + c] = make_float2(o10, o11);
            }
            if (s == S_ - 1 && want_hfinal) {
                float* hf = out + (size_t)S_ * BH_ + (size_t)layer * BH_;
                *(float2*)&hf[r0 * H_ + c] = make_float2(o00, o01);
                *(float2*)&hf[r1 * H_ + c] = make_float2(o10, o11);
            }
        }
        grid_sync(nblocks);
    }
}

__global__ void rnn_init() {
    int idx = blockIdx.x * blockDim.x + threadIdx.x;
    int stride = gridDim.x * blockDim.x;
    if (idx == 0) g_ctr_pre = 0;
    if (idx < S_) g_ctr[idx] = 0;
    for (int i = idx; i < LBH_; i += stride) g_h[0][i] = 0.0f;
}

extern "C" void kernel_launch(void* const* d_in, const int* in_sizes, int n_in,
                              void* d_out, int out_size) {
    const float* X    = (const float*)d_in[0];
    const float* W_xh = (const float*)d_in[1];
    const float* W_hh = (const float*)d_in[2];
    const float* b_h  = (const float*)d_in[3];
    const float* W_l  = (const float*)d_in[4];
    const float* U_l  = (const float*)d_in[5];
    const float* b_l  = (const float*)d_in[6];
    float* out = (float*)d_out;

    int nsm = 148;
    cudaDeviceGetAttribute(&nsm, cudaDevAttrMultiProcessorCount, 0);
    if (nsm < 1) nsm = 148;
    if (nsm > 512) nsm = 512;

    rnn_init<<<256, 256>>>();
    rnn_persistent<<<nsm, 256>>>(X, W_xh, W_hh, b_h, W_l, U_l, b_l, out,
                                 nsm, out_size);
}